// round 2
// baseline (speedup 1.0000x reference)
#include <cuda_runtime.h>
#include <cuda_bf16.h>
#include <cstdint>

#define EMB 64
#define NU 200000
#define NI 200000
#define NE 2000000
#define BATCH 16384

// ---------------- static device scratch (no runtime allocation) ----------------
__device__ int   g_slot_u[NU];
__device__ int   g_slot_i[NI];
__device__ float g_sA_u[NU];   // user_emb . Wa_u[64:]   (dst score, user side)
__device__ float g_sB_u[NU];   // user_emb . Wa_i[:64]   (src score, item side)
__device__ float g_sA_i[NI];   // item_emb . Wa_u[:64]   (src score, user side)
__device__ float g_sB_i[NI];   // item_emb . Wa_i[64:]   (dst score, item side)
__device__ float g_den_u[BATCH];
__device__ float g_den_i[BATCH];
__device__ __align__(16) float g_acc_u[BATCH * EMB];
__device__ __align__(16) float g_acc_i[BATCH * EMB];

// ---------------- helpers ----------------
__device__ __forceinline__ void red_add_v4(float* p, float4 v) {
    asm volatile("red.global.add.v4.f32 [%0], {%1,%2,%3,%4};"
                 :: "l"(p), "f"(v.x), "f"(v.y), "f"(v.z), "f"(v.w) : "memory");
}

// ---------------- 1) init scratch ----------------
__global__ void init_kernel() {
    int t = blockIdx.x * blockDim.x + threadIdx.x;
    int stride = gridDim.x * blockDim.x;
    for (int n = t; n < NU; n += stride) g_slot_u[n] = -1;
    for (int n = t; n < NI; n += stride) g_slot_i[n] = -1;
    for (int n = t; n < BATCH; n += stride) { g_den_u[n] = 0.f; g_den_i[n] = 0.f; }
    for (int n = t; n < BATCH * EMB; n += stride) { g_acc_u[n] = 0.f; g_acc_i[n] = 0.f; }
}

// ---------------- 2) node -> batch slot maps (dedups duplicate batch ids) ----------------
__global__ void slots_kernel(const int* __restrict__ u, const int* __restrict__ i) {
    int t = blockIdx.x * blockDim.x + threadIdx.x;
    if (t < BATCH) {
        atomicCAS(&g_slot_u[u[t]], -1, t);
    } else if (t < 2 * BATCH) {
        int b = t - BATCH;
        atomicCAS(&g_slot_i[i[b]], -1, b);
    }
}

// ---------------- 3) per-node attention scores (one pass over both tables) ----------------
__global__ void scores_kernel(const float* __restrict__ user_emb,
                              const float* __restrict__ item_emb,
                              const float* __restrict__ Wa_u,
                              const float* __restrict__ Wa_i) {
    int warp = (blockIdx.x * blockDim.x + threadIdx.x) >> 5;
    int lane = threadIdx.x & 31;
    if (warp < NU) {
        const float* e = user_emb + (size_t)warp * EMB;
        float a = e[lane], b = e[lane + 32];
        float s1 = a * Wa_u[64 + lane] + b * Wa_u[96 + lane];   // dst score, user side
        float s2 = a * Wa_i[lane]      + b * Wa_i[32 + lane];   // src score, item side
        #pragma unroll
        for (int o = 16; o; o >>= 1) {
            s1 += __shfl_xor_sync(0xffffffffu, s1, o);
            s2 += __shfl_xor_sync(0xffffffffu, s2, o);
        }
        if (lane == 0) { g_sA_u[warp] = s1; g_sB_u[warp] = s2; }
    } else if (warp < NU + NI) {
        int n = warp - NU;
        const float* e = item_emb + (size_t)n * EMB;
        float a = e[lane], b = e[lane + 32];
        float s1 = a * Wa_u[lane]      + b * Wa_u[32 + lane];   // src score, user side
        float s2 = a * Wa_i[64 + lane] + b * Wa_i[96 + lane];   // dst score, item side
        #pragma unroll
        for (int o = 16; o; o >>= 1) {
            s1 += __shfl_xor_sync(0xffffffffu, s1, o);
            s2 += __shfl_xor_sync(0xffffffffu, s2, o);
        }
        if (lane == 0) { g_sA_i[n] = s1; g_sB_i[n] = s2; }
    }
}

// ---------------- 4) edge pass: exp-weighted neighbor accumulation ----------------
// One pass: den[s] += exp(e); acc[s] += exp(e) * src_feat.  Max-subtraction skipped:
// logits bounded ~|0.6| (N(0,0.1^2) embeddings x 1/sqrt(128) weights), softmax is
// shift-invariant, fp32 exp is exact enough for rel_err 1e-3.
// SIDE 0: item->user (dst=user).  SIDE 1: user->item (dst=item).
template<int SIDE>
__global__ void edge_kernel(const int* __restrict__ src, const int* __restrict__ dst,
                            const float* __restrict__ feat) {
    const int*   slot  = SIDE == 0 ? g_slot_u : g_slot_i;
    const float* s_src = SIDE == 0 ? g_sA_i   : g_sB_u;
    const float* s_dst = SIDE == 0 ? g_sA_u   : g_sB_i;
    float*       den   = SIDE == 0 ? g_den_u  : g_den_i;
    float*       acc   = SIDE == 0 ? g_acc_u  : g_acc_i;

    int lane = threadIdx.x & 31;
    int e = blockIdx.x * blockDim.x + threadIdx.x;
    int myslot = -1, mysrc = 0;
    float w = 0.f;
    if (e < NE) {
        int d = dst[e];
        int s = slot[d];
        mysrc = src[e];
        if (s >= 0) {
            float att = s_src[mysrc] + s_dst[d];
            att = att > 0.f ? att : 0.01f * att;   // leaky_relu(0.01)
            w = __expf(att);
            myslot = s;
        }
    }
    unsigned act = __ballot_sync(0xffffffffu, myslot >= 0);
    while (act) {
        int l = __ffs(act) - 1;
        act &= act - 1;
        int   s  = __shfl_sync(0xffffffffu, myslot, l);
        float ww = __shfl_sync(0xffffffffu, w, l);
        int   sr = __shfl_sync(0xffffffffu, mysrc, l);
        if (lane == l) atomicAdd(&den[s], ww);
        if (lane < 16) {
            float4 f = reinterpret_cast<const float4*>(feat + (size_t)sr * EMB)[lane];
            float4 v = make_float4(ww * f.x, ww * f.y, ww * f.z, ww * f.w);
            red_add_v4(&acc[(size_t)s * EMB + lane * 4], v);
        }
    }
}

// ---------------- 5) fused per-row MLP ----------------
// warp-per-row; transposed weights in shared ([k*64+lane] is conflict-free: k is
// warp-uniform, lanes hit 32 distinct banks); x broadcast via shuffles.
__device__ __forceinline__ float2 matvec64(const float* sWT, float xlo, float xhi,
                                           float b0, float b1, int lane) {
    float a0 = b0, a1 = b1;
    #pragma unroll
    for (int k = 0; k < 32; k++) {
        float xk = __shfl_sync(0xffffffffu, xlo, k);
        a0 += xk * sWT[k * 64 + lane];
        a1 += xk * sWT[k * 64 + lane + 32];
    }
    #pragma unroll
    for (int k = 0; k < 32; k++) {
        float xk = __shfl_sync(0xffffffffu, xhi, k);
        a0 += xk * sWT[(k + 32) * 64 + lane];
        a1 += xk * sWT[(k + 32) * 64 + lane + 32];
    }
    return make_float2(a0, a1);
}

template<int SIDE>
__global__ void final_kernel(const int* __restrict__ ids, const float* __restrict__ emb_tab,
                             const float* __restrict__ Ws, const float* __restrict__ bs,
                             const float* __restrict__ Wn, const float* __restrict__ bn,
                             const float* __restrict__ Wfc,
                             float* __restrict__ out) {
    const int*   slot = SIDE == 0 ? g_slot_u : g_slot_i;
    const float* den  = SIDE == 0 ? g_den_u  : g_den_i;
    const float* acc  = SIDE == 0 ? g_acc_u  : g_acc_i;
    const int col_off = SIDE == 0 ? 0 : 64;

    extern __shared__ float sh[];
    float* sWsT  = sh;                  // 64*64
    float* sWnT  = sh + 64 * 64;        // 64*64
    float* sWfcT = sh + 2 * 64 * 64;    // 128*64
    for (int idx = threadIdx.x; idx < 64 * 64; idx += blockDim.x) {
        int j = idx >> 6, k = idx & 63;
        sWsT[k * 64 + j] = Ws[idx];
        sWnT[k * 64 + j] = Wn[idx];
    }
    for (int idx = threadIdx.x; idx < 64 * 128; idx += blockDim.x) {
        int j = idx >> 7, k = idx & 127;
        sWfcT[k * 64 + j] = Wfc[idx];
    }
    __syncthreads();

    int lane = threadIdx.x & 31;
    int warp = (blockIdx.x * blockDim.x + threadIdx.x) >> 5;
    int nwarps = (gridDim.x * blockDim.x) >> 5;
    float b_s0 = bs[lane], b_s1 = bs[lane + 32];
    float b_n0 = bn[lane], b_n1 = bn[lane + 32];

    for (int b = warp; b < BATCH; b += nwarps) {
        int node = ids[b];
        int s = slot[node];
        float dv = den[s];
        float inv = dv > 0.f ? 1.f / dv : 0.f;   // empty segment -> h = 0 (matches ref)
        float hlo = acc[(size_t)s * EMB + lane] * inv;
        float hhi = acc[(size_t)s * EMB + 32 + lane] * inv;
        float elo = emb_tab[(size_t)node * EMB + lane];
        float ehi = emb_tab[(size_t)node * EMB + 32 + lane];

        float2 sf = matvec64(sWsT, elo, ehi, b_s0, b_s1, lane);
        float2 nb = matvec64(sWnT, hlo, hhi, b_n0, b_n1, lane);
        float sf0 = fmaxf(sf.x, 0.f), sf1 = fmaxf(sf.y, 0.f);
        float nb0 = fmaxf(nb.x, 0.f), nb1 = fmaxf(nb.y, 0.f);

        // out[j] = relu( sum_k cat[k] * Wfc[j,k] ), cat = [sf(0:64), nb(64:128)]
        float a0 = 0.f, a1 = 0.f;
        #pragma unroll
        for (int k = 0; k < 32; k++) {
            float xk = __shfl_sync(0xffffffffu, sf0, k);
            a0 += xk * sWfcT[k * 64 + lane];
            a1 += xk * sWfcT[k * 64 + lane + 32];
        }
        #pragma unroll
        for (int k = 0; k < 32; k++) {
            float xk = __shfl_sync(0xffffffffu, sf1, k);
            a0 += xk * sWfcT[(k + 32) * 64 + lane];
            a1 += xk * sWfcT[(k + 32) * 64 + lane + 32];
        }
        #pragma unroll
        for (int k = 0; k < 32; k++) {
            float xk = __shfl_sync(0xffffffffu, nb0, k);
            a0 += xk * sWfcT[(k + 64) * 64 + lane];
            a1 += xk * sWfcT[(k + 64) * 64 + lane + 32];
        }
        #pragma unroll
        for (int k = 0; k < 32; k++) {
            float xk = __shfl_sync(0xffffffffu, nb1, k);
            a0 += xk * sWfcT[(k + 96) * 64 + lane];
            a1 += xk * sWfcT[(k + 96) * 64 + lane + 32];
        }
        out[(size_t)b * 128 + col_off + lane]      = fmaxf(a0, 0.f);
        out[(size_t)b * 128 + col_off + 32 + lane] = fmaxf(a1, 0.f);
    }
}

// ---------------- launch ----------------
extern "C" void kernel_launch(void* const* d_in, const int* in_sizes, int n_in,
                              void* d_out, int out_size) {
    const float* user_emb = (const float*)d_in[0];
    const float* item_emb = (const float*)d_in[1];
    const float* Wa_u = (const float*)d_in[2];
    const float* Wa_i = (const float*)d_in[3];
    const float* Wfc_u = (const float*)d_in[4];
    const float* Wfc_i = (const float*)d_in[5];
    const float* Ws_u = (const float*)d_in[6];
    const float* bs_u = (const float*)d_in[7];
    const float* Ws_i = (const float*)d_in[8];
    const float* bs_i = (const float*)d_in[9];
    const float* Wn_u = (const float*)d_in[10];
    const float* bn_u = (const float*)d_in[11];
    const float* Wn_i = (const float*)d_in[12];
    const float* bn_i = (const float*)d_in[13];
    const int* u      = (const int*)d_in[14];
    const int* iid    = (const int*)d_in[15];
    const int* src_iu = (const int*)d_in[16];
    const int* dst_iu = (const int*)d_in[17];
    const int* src_ui = (const int*)d_in[18];
    const int* dst_ui = (const int*)d_in[19];
    float* out = (float*)d_out;

    const int SMEM_FINAL = (2 * 64 * 64 + 128 * 64) * sizeof(float);  // 65536 B
    static bool attr_set = false;
    if (!attr_set) {
        cudaFuncSetAttribute(final_kernel<0>, cudaFuncAttributeMaxDynamicSharedMemorySize, SMEM_FINAL);
        cudaFuncSetAttribute(final_kernel<1>, cudaFuncAttributeMaxDynamicSharedMemorySize, SMEM_FINAL);
        attr_set = true;
    }

    // 1) init scratch
    init_kernel<<<1024, 256>>>();
    // 2) slot maps
    slots_kernel<<<(2 * BATCH + 255) / 256, 256>>>(u, iid);
    // 3) per-node scores (warp per node, both tables in one launch)
    {
        long threads = (long)(NU + NI) * 32;
        int blocks = (int)((threads + 255) / 256);
        scores_kernel<<<blocks, 256>>>(user_emb, item_emb, Wa_u, Wa_i);
    }
    // 4) edge passes (1 thread/edge, warp-cooperative float4 gather + vector L2 reduction)
    {
        int blocks = (NE + 255) / 256;
        edge_kernel<0><<<blocks, 256>>>(src_iu, dst_iu, item_emb);
        edge_kernel<1><<<blocks, 256>>>(src_ui, dst_ui, user_emb);
    }
    // 5) fused MLP heads
    final_kernel<0><<<512, 256, SMEM_FINAL>>>(u, user_emb, Ws_u, bs_u, Wn_u, bn_u, Wfc_u, out);
    final_kernel<1><<<512, 256, SMEM_FINAL>>>(iid, item_emb, Ws_i, bs_i, Wn_i, bn_i, Wfc_i, out);
}